// round 12
// baseline (speedup 1.0000x reference)
#include <cuda_runtime.h>
#include <cuda_fp16.h>
#include <cstdint>
#include <math.h>

// Problem constants (R=1024, S=128, J=24, H=64, multires=6)
constexpr int NPTS = 1024 * 128;
constexpr int NJ   = 24;
constexpr int NH   = 64;
constexpr int NI   = 39;
constexpr int NPH  = 12;     // phases: 2 joints each
constexpr int KP   = 80;     // K per phase: 39 + 1 pad + 39 + 1 pad
constexpr int MT   = 256;    // points per CTA
constexpr int ASTR = 176;    // A row stride bytes (80 cols * 2B = 160, pad to 176)
constexpr int BSTR = 144;    // B row stride bytes (64 cols * 2B = 128, pad to 144)

// ---- dynamic SMEM layout ----
constexpr int SM_A   = 0;                       // A fp16: 256 x 176 = 45056
constexpr int SM_B0  = 45056;                   // 80 x 144 = 11520
constexpr int SM_B1  = 56576;
constexpr int SM_TR  = 68096;                   // 24x16 f32 = 1536
constexpr int SM_W1  = 69632;                   // 64x24 f32 = 6144
constexpr int SM_SZ  = 75776;
// epilogue overlay: H[256 x 65 f32] = 66560B at 0 (over A+B0+B1; < SM_TR)

// relu(h) row-major [NPTS, NJ]; warp_kernel reads the faithful view(J,-1).T
// scramble as linear index j*NPTS + m.
__device__ float g_h[(size_t)NPTS * NJ];
// fp16 B images per phase: [80 k][72 n-stride] (byte image of the smem tile)
__device__ __align__(16) unsigned short g_Bh[NPH * KP * 72];

// ---------------- helpers ----------------
__device__ __forceinline__ uint32_t smem_u32(const void* p) {
    uint32_t a;
    asm("{ .reg .u64 t; cvta.to.shared.u64 t, %1; cvt.u32.u64 %0, t; }" : "=r"(a) : "l"(p));
    return a;
}
__device__ __forceinline__ void ldsm4(uint32_t* r, uint32_t addr) {
    asm volatile("ldmatrix.sync.aligned.m8n8.x4.shared.b16 {%0,%1,%2,%3}, [%4];"
                 : "=r"(r[0]), "=r"(r[1]), "=r"(r[2]), "=r"(r[3]) : "r"(addr));
}
__device__ __forceinline__ void ldsm4t(uint32_t* r, uint32_t addr) {
    asm volatile("ldmatrix.sync.aligned.m8n8.x4.trans.shared.b16 {%0,%1,%2,%3}, [%4];"
                 : "=r"(r[0]), "=r"(r[1]), "=r"(r[2]), "=r"(r[3]) : "r"(addr));
}
__device__ __forceinline__ void mma16816h(float* d, const uint32_t* a,
                                          uint32_t b0, uint32_t b1) {
    asm volatile(
        "mma.sync.aligned.m16n8k16.row.col.f32.f16.f16.f32 "
        "{%0,%1,%2,%3}, {%4,%5,%6,%7}, {%8,%9}, {%0,%1,%2,%3};"
        : "+f"(d[0]), "+f"(d[1]), "+f"(d[2]), "+f"(d[3])
        : "r"(a[0]), "r"(a[1]), "r"(a[2]), "r"(a[3]), "r"(b0), "r"(b1));
}
// pack two f32 -> f16x2 (a in low half)
__device__ __forceinline__ uint32_t packh2(float a, float b) {
    uint32_t r;
    asm("cvt.rn.f16x2.f32 %0, %1, %2;" : "=r"(r) : "f"(b), "f"(a));
    return r;
}

// ---------------------------------------------------------------------------
// Prep: per-phase B tiles: k rows 0..38 = joint 2p, 39 zero, 40..78 = joint
// 2p+1, 79 zero.  B[k][n] = fp16(w0[(j*39+k)*64 + n]); pad cols zeroed.
// ---------------------------------------------------------------------------
__global__ void prep_b(const float* __restrict__ w0) {
    int idx = blockIdx.x * 256 + threadIdx.x;
    if (idx >= NPH * KP * 72) return;
    int p = idx / (KP * 72), rem = idx % (KP * 72);
    int kk = rem / 72, n = rem % 72;
    float v = 0.f;
    if (n < NH) {
        if (kk < NI)                  v = w0[((2 * p)     * NI + kk)        * NH + n];
        else if (kk >= 40 && kk < 79) v = w0[((2 * p + 1) * NI + (kk - 40)) * NH + n];
    }
    g_Bh[p * (KP * 72) + kk * 72 + n] = __half_as_ushort(__float2half_rn(v));
}

// ---------------------------------------------------------------------------
// Kernel 1: 256-pt tile, 256 threads (8 warps), 2 CTAs/SM.
// Phase: stage B(p) | sync | features (both joints) streamed to A | sync |
// gemm(p).  Warp w: rows [w*32,+32) x ALL 64 cols (A ldsm'd once).
// ---------------------------------------------------------------------------
__global__ __launch_bounds__(256, 2)
void weights_mma(const float* __restrict__ xyz,
                 const float* __restrict__ transforms,
                 const float* __restrict__ w1)
{
    extern __shared__ __align__(16) char sm[];
    const uint32_t sb = smem_u32(sm);
    const int tid = threadIdx.x, lane = tid & 31, w = tid >> 5;
    const int n = blockIdx.x * MT + tid;
    const int oct = lane >> 3, oi = lane & 7;

    for (int i = tid; i < NJ * 16; i += 256)
        ((float*)(sm + SM_TR))[i] = transforms[i];
    __syncthreads();

    const float x = xyz[3 * n + 0];
    const float y = xyz[3 * n + 1];
    const float z = xyz[3 * n + 2];

    float acc[2][8][4];
#pragma unroll
    for (int a = 0; a < 2; ++a)
#pragma unroll
        for (int b = 0; b < 8; ++b)
#pragma unroll
            for (int c = 0; c < 4; ++c) acc[a][b][c] = 0.f;

    for (int p = 0; p < NPH; ++p) {
        const int bB = (p & 1) ? SM_B1 : SM_B0;

        // stage B(p) into buffer p&1 — gemm(p-1) reads the OTHER buffer
        {
            const uint4* shp = (const uint4*)(g_Bh + p * (KP * 72));
            uint4* dh = (uint4*)(sm + bB);
            for (int i = tid; i < 720; i += 256) dh[i] = shp[i];
        }
        __syncthreads();   // gemm(p-1) done reading A (and B stage visible)

        // features for BOTH joints of this phase, streamed into A row pt=tid
#pragma unroll
        for (int half = 0; half < 2; ++half) {
            const int j = 2 * p + half;
            const float* T = (const float*)(sm + SM_TR) + j * 16;
            float lx = fmaf(T[0], x, fmaf(T[1], y, fmaf(T[2],  z, T[3])));
            float ly = fmaf(T[4], x, fmaf(T[5], y, fmaf(T[6],  z, T[7])));
            float lz = fmaf(T[8], x, fmaf(T[9], y, fmaf(T[10], z, T[11])));
            const float INV = 2.0f / 3.0f;
            lx = (lx + 1.5f) * INV - 1.0f;
            ly = (ly + 1.5f) * INV - 1.0f;
            lz = (lz + 1.5f) * INV - 1.0f;
            uint32_t fp[20];
            fp[0] = packh2(lx, ly);
            float carry = lz;
            float sx, cx, sy, cy, sz, cz;
            __sincosf(lx, &sx, &cx);
            __sincosf(ly, &sy, &cy);
            __sincosf(lz, &sz, &cz);
#pragma unroll
            for (int ff = 0; ff < 6; ++ff) {
                fp[1 + 3 * ff] = packh2(carry, sx);
                fp[2 + 3 * ff] = packh2(sy, sz);
                fp[3 + 3 * ff] = packh2(cx, cy);
                carry = cz;
                if (ff < 5) {
                    // sin(2a) = 2 s c ; cos(2a) = 1 - 2 s^2
                    float nsx = 2.f * sx * cx, ncx = fmaf(-2.f * sx, sx, 1.f);
                    float nsy = 2.f * sy * cy, ncy = fmaf(-2.f * sy, sy, 1.f);
                    float nsz = 2.f * sz * cz, ncz = fmaf(-2.f * sz, sz, 1.f);
                    sx = nsx; cx = ncx; sy = nsy; cy = ncy; sz = nsz; cz = ncz;
                }
            }
            fp[19] = packh2(carry, 0.f);            // cz5 + pad column
#pragma unroll
            for (int c = 0; c < 5; ++c) {
                uint4 H = make_uint4(fp[4 * c + 0], fp[4 * c + 1],
                                     fp[4 * c + 2], fp[4 * c + 3]);
                *(uint4*)(sm + SM_A + tid * ASTR + half * 80 + c * 16) = H;
            }
        }
        __syncthreads();   // A + B staged

        // gemm(p): warp w = rows [w*32,+32) x cols [0,64)
#pragma unroll
        for (int ks = 0; ks < 5; ++ks) {
            uint32_t ah[2][4];
#pragma unroll
            for (int mt = 0; mt < 2; ++mt) {
                uint32_t ra = (uint32_t)((w * 32 + mt * 16 + (oct & 1) * 8 + oi) * ASTR
                                         + ks * 32 + (oct >> 1) * 16);
                ldsm4(ah[mt], sb + SM_A + ra);
            }
#pragma unroll
            for (int np = 0; np < 4; ++np) {
                uint32_t rb = (uint32_t)((ks * 16 + (oct & 1) * 8 + oi) * BSTR
                                         + np * 32 + (oct >> 1) * 16);
                uint32_t bh[4];
                ldsm4t(bh, sb + bB + rb);
#pragma unroll
                for (int mt = 0; mt < 2; ++mt) {
                    mma16816h(acc[mt][2 * np + 0], ah[mt], bh[0], bh[1]);
                    mma16816h(acc[mt][2 * np + 1], ah[mt], bh[2], bh[3]);
                }
            }
        }
    }
    __syncthreads();   // all warps done with A/B regions

    // Epilogue: relu(acc) -> H smem [256 x 64], stride 65 f32 (overlays A/B)
    float* hs = (float*)(sm + 0);
#pragma unroll
    for (int mt = 0; mt < 2; ++mt) {
        const int rr = w * 32 + mt * 16 + (lane >> 2);
#pragma unroll
        for (int nt = 0; nt < 8; ++nt) {
            const int cc = nt * 8 + (lane & 3) * 2;
            hs[rr * 65 + cc]           = fmaxf(acc[mt][nt][0], 0.f);
            hs[rr * 65 + cc + 1]       = fmaxf(acc[mt][nt][1], 0.f);
            hs[(rr + 8) * 65 + cc]     = fmaxf(acc[mt][nt][2], 0.f);
            hs[(rr + 8) * 65 + cc + 1] = fmaxf(acc[mt][nt][3], 0.f);
        }
    }
    for (int i = tid; i < (NH * NJ) / 4; i += 256)
        ((float4*)(sm + SM_W1))[i] = ((const float4*)w1)[i];
    __syncthreads();

    // Layer 2 + relu: thread tid does row tid, all 24 joints
    const float* myrow = hs + tid * 65;
    float ra[NH];
#pragma unroll
    for (int k = 0; k < NH; ++k) ra[k] = myrow[k];

    const float* sw1 = (const float*)(sm + SM_W1);
    float* gout = &g_h[(size_t)n * NJ];
#pragma unroll 1
    for (int jj = 0; jj < NJ; ++jj) {
        float s = 0.f;
#pragma unroll
        for (int k = 0; k < NH; ++k) s = fmaf(ra[k], sw1[k * NJ + jj], s);
        gout[jj] = fmaxf(s, 0.f);
    }
}

// ---------------------------------------------------------------------------
// Kernel 2: scrambled-weight readback + normalized transform blend
// ---------------------------------------------------------------------------
__global__ __launch_bounds__(256)
void warp_kernel(const float* __restrict__ xyz,
                 const float* __restrict__ vdir,
                 const float* __restrict__ transforms,
                 float* __restrict__ out)
{
    __shared__ float str[NJ * 16];
    const int tid = threadIdx.x;
    const int m   = blockIdx.x * 256 + tid;
    for (int i = tid; i < NJ * 16; i += 256) str[i] = transforms[i];
    __syncthreads();

    float w[NJ];
    float s = 0.f;
#pragma unroll
    for (int j = 0; j < NJ; ++j) {
        w[j] = g_h[(size_t)j * NPTS + m];
        s += w[j];
    }
    const float inv = 1.0f / (s + 1e-6f);

    const float x  = xyz[3 * m + 0], y  = xyz[3 * m + 1], z  = xyz[3 * m + 2];
    const float vx = vdir[3 * m + 0], vy = vdir[3 * m + 1], vz = vdir[3 * m + 2];
    const float x2 = x - vx, y2 = y - vy, z2 = z - vz;

    float a1x = 0.f, a1y = 0.f, a1z = 0.f;
    float a2x = 0.f, a2y = 0.f, a2z = 0.f;
#pragma unroll
    for (int j = 0; j < NJ; ++j) {
        const float wn = w[j] * inv;
        const float* T = &str[j * 16];
        a1x = fmaf(wn, fmaf(T[0], x,  fmaf(T[1], y,  fmaf(T[2],  z,  T[3]))),  a1x);
        a1y = fmaf(wn, fmaf(T[4], x,  fmaf(T[5], y,  fmaf(T[6],  z,  T[7]))),  a1y);
        a1z = fmaf(wn, fmaf(T[8], x,  fmaf(T[9], y,  fmaf(T[10], z,  T[11]))), a1z);
        a2x = fmaf(wn, fmaf(T[0], x2, fmaf(T[1], y2, fmaf(T[2],  z2, T[3]))),  a2x);
        a2y = fmaf(wn, fmaf(T[4], x2, fmaf(T[5], y2, fmaf(T[6],  z2, T[7]))),  a2y);
        a2z = fmaf(wn, fmaf(T[8], x2, fmaf(T[9], y2, fmaf(T[10], z2, T[11]))), a2z);
    }

    out[3 * m + 0] = a1x;
    out[3 * m + 1] = a1y;
    out[3 * m + 2] = a1z;
    float* o2 = out + (size_t)3 * NPTS;
    o2[3 * m + 0] = a1x - a2x;
    o2[3 * m + 1] = a1y - a2y;
    o2[3 * m + 2] = a1z - a2z;
}

// ---------------------------------------------------------------------------
// Inputs: xyz_sampled, viewdirs, transforms, ray_valid(unused), w0, w1
// ---------------------------------------------------------------------------
extern "C" void kernel_launch(void* const* d_in, const int* in_sizes, int n_in,
                              void* d_out, int out_size)
{
    const float* xyz = (const float*)d_in[0];
    const float* vd  = (const float*)d_in[1];
    const float* tr  = (const float*)d_in[2];
    const float* w0  = (const float*)d_in[4];
    const float* w1  = (const float*)d_in[5];
    float* out = (float*)d_out;

    // Unconditional every call: deterministic, not a stream op (capture-safe).
    cudaFuncSetAttribute(weights_mma, cudaFuncAttributeMaxDynamicSharedMemorySize, SM_SZ);

    prep_b<<<(NPH * KP * 72 + 255) / 256, 256>>>(w0);
    weights_mma<<<NPTS / MT, 256, SM_SZ>>>(xyz, tr, w1);
    warp_kernel<<<NPTS / 256, 256>>>(xyz, vd, tr, out);
}